// round 16
// baseline (speedup 1.0000x reference)
#include <cuda_runtime.h>
#include <cuda_bf16.h>

#define SCALING 0.17677669529663687f

// ---------------------------------------------------------------------------
// Scratch (static device globals — allowed; no runtime allocation)
// g_projp[j][bh][s][k]: .x = bf16x2 hi(dims 2k,2k+1), .y = bf16x2 lo
// ---------------------------------------------------------------------------
__device__ uint2 g_projp[9][32][1024][16];          // interleaved hi/lo planes
__device__ float g_v[32][1024][32];                 // V fp32 (AV)
__device__ float g_mask[32][1024 * 1024];           // local_mask
__device__ float g_attn_pre[4096 * 256];            // pre-out-proj fp32

// ---------------------------------------------------------------------------
// mma.sync m16n8k16 bf16 (HMMA), D/C fp32
// ---------------------------------------------------------------------------
__device__ __forceinline__ void mma_bf16(
    float& d0, float& d1, float& d2, float& d3,
    unsigned a0, unsigned a1, unsigned a2, unsigned a3,
    unsigned b0, unsigned b1)
{
    asm volatile(
        "mma.sync.aligned.m16n8k16.row.col.f32.bf16.bf16.f32 "
        "{%0,%1,%2,%3}, {%4,%5,%6,%7}, {%8,%9}, {%0,%1,%2,%3};\n"
        : "+f"(d0), "+f"(d1), "+f"(d2), "+f"(d3)
        : "r"(a0), "r"(a1), "r"(a2), "r"(a3), "r"(b0), "r"(b1));
}
__device__ __forceinline__ unsigned s2u(const void* p) {
    unsigned a;
    asm("{ .reg .u64 t; cvta.to.shared.u64 t, %1; cvt.u32.u64 %0, t; }"
        : "=r"(a) : "l"(p));
    return a;
}
__device__ __forceinline__ void ldsm_x4(unsigned r[4], unsigned addr) {
    asm volatile("ldmatrix.sync.aligned.m8n8.x4.shared.b16 {%0,%1,%2,%3}, [%4];"
        : "=r"(r[0]), "=r"(r[1]), "=r"(r[2]), "=r"(r[3]) : "r"(addr));
}
__device__ __forceinline__ unsigned packbf2(__nv_bfloat16 a, __nv_bfloat16 b) {
    __nv_bfloat162 p; p.x = a; p.y = b;
    return *(unsigned*)&p;
}

// ---------------------------------------------------------------------------
// warp helpers (R6-proven)
// ---------------------------------------------------------------------------
__device__ __forceinline__ void warp_iscan2(float& a, float& b, int lane) {
    #pragma unroll
    for (int o = 1; o < 32; o <<= 1) {
        float ua = __shfl_up_sync(0xffffffffu, a, o);
        float ub = __shfl_up_sync(0xffffffffu, b, o);
        if (lane >= o) { a += ua; b += ub; }
    }
}
__device__ __forceinline__ void warp_softmax_row2(float* r0, float* r1, int lane) {
    float m0 = -1e30f, m1 = -1e30f;
    #pragma unroll
    for (int q = 0; q < 32; q++) {
        m0 = fmaxf(m0, r0[q * 32 + lane]);
        m1 = fmaxf(m1, r1[q * 32 + lane]);
    }
    #pragma unroll
    for (int o = 16; o; o >>= 1) {
        m0 = fmaxf(m0, __shfl_xor_sync(0xffffffffu, m0, o));
        m1 = fmaxf(m1, __shfl_xor_sync(0xffffffffu, m1, o));
    }
    float s0 = 0.f, s1 = 0.f;
    #pragma unroll
    for (int q = 0; q < 32; q++) {
        float e0 = __expf(r0[q * 32 + lane] - m0);
        float e1 = __expf(r1[q * 32 + lane] - m1);
        r0[q * 32 + lane] = e0;
        r1[q * 32 + lane] = e1;
        s0 += e0; s1 += e1;
    }
    #pragma unroll
    for (int o = 16; o; o >>= 1) {
        s0 += __shfl_xor_sync(0xffffffffu, s0, o);
        s1 += __shfl_xor_sync(0xffffffffu, s1, o);
    }
    float i0 = 1.0f / s0, i1 = 1.0f / s1;
    #pragma unroll
    for (int q = 0; q < 32; q++) {
        r0[q * 32 + lane] *= i0;
        r1[q * 32 + lane] *= i1;
    }
}

// ---------------------------------------------------------------------------
// convert helper: float4 -> 4 hi bf16 + 4 lo bf16 (smem staging)
// ---------------------------------------------------------------------------
__device__ __forceinline__ void split_store4(char* dh, char* dl, float4 v) {
    __nv_bfloat16 h0 = __float2bfloat16(v.x);
    __nv_bfloat16 h1 = __float2bfloat16(v.y);
    __nv_bfloat16 h2 = __float2bfloat16(v.z);
    __nv_bfloat16 h3 = __float2bfloat16(v.w);
    *(unsigned*)(dh)     = packbf2(h0, h1);
    *(unsigned*)(dh + 4) = packbf2(h2, h3);
    *(unsigned*)(dl)     = packbf2(__float2bfloat16(v.x - __bfloat162float(h0)),
                                   __float2bfloat16(v.y - __bfloat162float(h1)));
    *(unsigned*)(dl + 4) = packbf2(__float2bfloat16(v.z - __bfloat162float(h2)),
                                   __float2bfloat16(v.w - __bfloat162float(h3)));
}

// ===========================================================================
// Shared staged-HMMA GEMM body, DOUBLE-BUFFERED (R15-proven):
// C[128 x 64] tile of  Xf32 @ Wf32^T.  Two 30720 B buffers.
// ===========================================================================
#define BUF_SZ 30720

__device__ __forceinline__ void stage_buf(char* buf,
        const float* __restrict__ Xbase, const float* __restrict__ Wbase,
        int ch, int t)
{
    char* SAh = buf;
    char* SAl = buf + 10240;
    char* SBh = buf + 20480;
    char* SBl = buf + 25600;
    int r = t >> 3, c = (t & 7) * 4;
    #pragma unroll
    for (int p = 0; p < 4; p++) {
        int rr = r + p * 32;
        float4 v = *(const float4*)(Xbase + (size_t)rr * 256 + ch * 32 + c);
        split_store4(SAh + rr * 80 + c * 2, SAl + rr * 80 + c * 2, v);
    }
    #pragma unroll
    for (int p = 0; p < 2; p++) {
        int rr = r + p * 32;
        float4 v = *(const float4*)(Wbase + (size_t)rr * 256 + ch * 32 + c);
        split_store4(SBh + rr * 80 + c * 2, SBl + rr * 80 + c * 2, v);
    }
}

__device__ __forceinline__ void staged_hmma_128x64(
        const float* __restrict__ Xbase, const float* __restrict__ Wbase,
        char* smc, int t, int lane, int w, float acc[2][4][4])
{
    int wm = w & 3, wn = w >> 2;

    #pragma unroll
    for (int a = 0; a < 2; a++)
        #pragma unroll
        for (int b = 0; b < 4; b++)
            #pragma unroll
            for (int c = 0; c < 4; c++) acc[a][b][c] = 0.f;

    stage_buf(smc, Xbase, Wbase, 0, t);
    __syncthreads();

    #pragma unroll 1
    for (int ch = 0; ch < 8; ch++) {
        char* cur = smc + (ch & 1) * BUF_SZ;
        char* nxt = smc + ((ch + 1) & 1) * BUF_SZ;
        if (ch < 7) stage_buf(nxt, Xbase, Wbase, ch + 1, t);

        char* SBh = cur + 20480;
        char* SBl = cur + 25600;
        unsigned sAh = s2u(cur), sAl = s2u(cur + 10240);

        unsigned ah[2][2][4], al[2][2][4];
        #pragma unroll
        for (int rt2 = 0; rt2 < 2; rt2++) {
            unsigned off = (unsigned)((wm * 32 + rt2 * 16 + (lane & 15)) * 80
                                      + (lane >> 4) * 16);
            ldsm_x4(ah[rt2][0], sAh + off);
            ldsm_x4(ah[rt2][1], sAh + off + 32);
            ldsm_x4(al[rt2][0], sAl + off);
            ldsm_x4(al[rt2][1], sAl + off + 32);
        }
        #pragma unroll
        for (int g = 0; g < 4; g++) {
            int nr = wn * 32 + g * 8 + (lane >> 2);
            int cb = (lane & 3) * 4;
            #pragma unroll
            for (int ks = 0; ks < 2; ks++) {
                unsigned bh0 = *(const unsigned*)(SBh + nr * 80 + cb + ks * 32);
                unsigned bh1 = *(const unsigned*)(SBh + nr * 80 + cb + ks * 32 + 16);
                unsigned bl0 = *(const unsigned*)(SBl + nr * 80 + cb + ks * 32);
                unsigned bl1 = *(const unsigned*)(SBl + nr * 80 + cb + ks * 32 + 16);
                #pragma unroll
                for (int rt2 = 0; rt2 < 2; rt2++) {
                    mma_bf16(acc[rt2][g][0], acc[rt2][g][1], acc[rt2][g][2], acc[rt2][g][3],
                             ah[rt2][ks][0], ah[rt2][ks][1], ah[rt2][ks][2], ah[rt2][ks][3],
                             bh0, bh1);
                    mma_bf16(acc[rt2][g][0], acc[rt2][g][1], acc[rt2][g][2], acc[rt2][g][3],
                             al[rt2][ks][0], al[rt2][ks][1], al[rt2][ks][2], al[rt2][ks][3],
                             bh0, bh1);
                    mma_bf16(acc[rt2][g][0], acc[rt2][g][1], acc[rt2][g][2], acc[rt2][g][3],
                             ah[rt2][ks][0], ah[rt2][ks][1], ah[rt2][ks][2], ah[rt2][ks][3],
                             bl0, bl1);
                }
            }
        }
        __syncthreads();
    }
}

// ---------------------------------------------------------------------------
// Kernel 1: packed in-projection (staged HMMA) -> interleaved planes + g_v
// ---------------------------------------------------------------------------
__global__ void __launch_bounds__(256) proj_hmma_kernel(
        const float* __restrict__ xq, const float* __restrict__ xk,
        const float* __restrict__ xv, const float* __restrict__ W,
        const float* __restrict__ bias)
{
    extern __shared__ char smc[];
    int ct = blockIdx.x, rt = blockIdx.y;
    int j = ct >> 2;
    const float* X = (j == 2) ? xv
                   : ((j == 1 || j == 4 || j == 6 || j == 8) ? xk : xq);
    int t = threadIdx.x, lane = t & 31, w = t >> 5;
    int wm = w & 3, wn = w >> 2;

    float acc[2][4][4];
    staged_hmma_128x64(X + (size_t)(rt * 128) * 256,
                       W + (size_t)(ct * 64) * 256, smc, t, lane, w, acc);

    float scale = (j == 0 || j == 7) ? SCALING : 1.0f;
    #pragma unroll
    for (int rt2 = 0; rt2 < 2; rt2++) {
        int rbase = rt * 128 + wm * 32 + rt2 * 16 + (lane >> 2);
        #pragma unroll
        for (int g = 0; g < 4; g++) {
            int cbase = ct * 64 + wn * 32 + g * 8 + (lane & 3) * 2;
            int eo = cbase - j * 256;
            #pragma unroll
            for (int half = 0; half < 2; half++) {
                int r = rbase + half * 8;
                float v0 = (acc[rt2][g][half * 2 + 0] + bias[cbase]) * scale;
                float v1 = (acc[rt2][g][half * 2 + 1] + bias[cbase + 1]) * scale;
                int s = r >> 2, b = r & 3;
                int bhp = b * 8 + (eo >> 5), dd = eo & 31;
                __nv_bfloat16 h0 = __float2bfloat16(v0);
                __nv_bfloat16 h1 = __float2bfloat16(v1);
                uint2 val;
                val.x = packbf2(h0, h1);
                val.y = packbf2(__float2bfloat16(v0 - __bfloat162float(h0)),
                                __float2bfloat16(v1 - __bfloat162float(h1)));
                g_projp[j][bhp][s][dd >> 1] = val;
                if (j == 2) *(float2*)&g_v[bhp][s][dd] = make_float2(v0, v1);
            }
        }
    }
}

// ---------------------------------------------------------------------------
// Kernel F1: per (bh, 16 rows), 512 threads / 16 warps (R12-proven)
// ---------------------------------------------------------------------------
__global__ void __launch_bounds__(512, 1) f1_kernel()
{
    extern __shared__ float sm[];
    float* Ls = sm;                  // 16 x 1024
    float* Rs = sm + 16384;          // 16 x 1024
    int t = threadIdx.x, lane = t & 31, w = t >> 5;   // w: 0..15
    int rt = blockIdx.x, bh = blockIdx.y;
    int row0 = rt * 16;
    int n = lane >> 2, pi = lane & 3;

    unsigned B[2][2][2][2][2];
    #pragma unroll
    for (int m = 0; m < 2; m++) {
        int slice = m ? 5 : 3;
        #pragma unroll
        for (int rh = 0; rh < 2; rh++) {
            const uint2* qp = g_projp[slice][bh][row0 + rh * 8 + n];
            uint2 u0 = qp[pi],     u1 = qp[pi + 4];
            uint2 u2 = qp[pi + 8], u3 = qp[pi + 12];
            B[m][rh][0][0][0] = u0.x; B[m][rh][1][0][0] = u0.y;
            B[m][rh][0][0][1] = u1.x; B[m][rh][1][0][1] = u1.y;
            B[m][rh][0][1][0] = u2.x; B[m][rh][1][1][0] = u2.y;
            B[m][rh][0][1][1] = u3.x; B[m][rh][1][1][1] = u3.y;
        }
    }

    #pragma unroll 1
    for (int m = 0; m < 2; m++) {
        const uint2* Kp = &g_projp[m ? 6 : 4][bh][0][0];
        float* Obuf = m ? Rs : Ls;
        #pragma unroll 1
        for (int j = 0; j < 4; j++) {
            int col0 = (j * 16 + w) * 16;
            const uint2* r0p = Kp + (size_t)(col0 + n) * 16;
            const uint2* r1p = Kp + (size_t)(col0 + n + 8) * 16;
            float d[2][4] = {};
            #pragma unroll
            for (int ks = 0; ks < 2; ks++) {
                int ip = ks * 8 + pi;
                uint2 a0 = r0p[ip],     a1 = r1p[ip];
                uint2 a2 = r0p[ip + 4], a3 = r1p[ip + 4];
                #pragma unroll
                for (int rh = 0; rh < 2; rh++) {
                    mma_bf16(d[rh][0], d[rh][1], d[rh][2], d[rh][3],
                             a0.x, a1.x, a2.x, a3.x,
                             B[m][rh][0][ks][0], B[m][rh][0][ks][1]);
                    mma_bf16(d[rh][0], d[rh][1], d[rh][2], d[rh][3],
                             a0.y, a1.y, a2.y, a3.y,
                             B[m][rh][0][ks][0], B[m][rh][0][ks][1]);
                    mma_bf16(d[rh][0], d[rh][1], d[rh][2], d[rh][3],
                             a0.x, a1.x, a2.x, a3.x,
                             B[m][rh][1][ks][0], B[m][rh][1][ks][1]);
                }
            }
            int c = col0 + n;
            #pragma unroll
            for (int rh = 0; rh < 2; rh++) {
                int q = rh * 8 + pi * 2;
                Obuf[q * 1024 + c]           = d[rh][0];
                Obuf[(q + 1) * 1024 + c]     = d[rh][1];
                Obuf[q * 1024 + c + 8]       = d[rh][2];
                Obuf[(q + 1) * 1024 + c + 8] = d[rh][3];
            }
        }
    }
    __syncthreads();

    float* Lrow = Ls + w * 1024;
    float* Rrow = Rs + w * 1024;
    warp_softmax_row2(Lrow, Rrow, lane);

    float sL[32], sR[32];
    float runPL = 0.f, runPR = 0.f;
    #pragma unroll
    for (int q = 0; q < 32; q++) {
        float vL = Lrow[q * 32 + lane];
        float vR = Rrow[q * 32 + lane];
        float pL = vL, pR = vR;
        warp_iscan2(pL, pR, lane);
        float BL = __shfl_sync(0xffffffffu, pL, 31);
        float BR = __shfl_sync(0xffffffffu, pR, 31);
        runPL += pL;
        runPR += pR;
        Lrow[q * 32 + lane] = runPL;
        Rrow[q * 32 + lane] = runPR;
        sL[q] = BL - pL + vL;
        sR[q] = BR - pR + vR;
    }
    float* mout = &g_mask[bh][(size_t)(row0 + w) * 1024];
    float runSL = 0.f, runSR = 0.f;
    #pragma unroll
    for (int q = 31; q >= 0; q--) {
        runSL += sL[q];
        runSR += sR[q];
        mout[q * 32 + lane] = Lrow[q * 32 + lane] * runSR
                            + runSL * Rrow[q * 32 + lane];
    }
}

// ---------------------------------------------------------------------------
// Kernel F2: per (bh, 32 rows), 512 threads / 16 warps.
// Two-pass logits (pass0: global -> Cs=0.1*g; pass1: local -> Cs += lc*mask)
// keeps registers ~80 at 512 threads.  K L2 traffic halved vs 16-row CTA.
// Then softmax + SIMT AV with j-slice partials.
// smem: Cs 32x1024 (131072 B) + Ps 16x1024 (65536 B) = 196608 B, 1 CTA/SM.
// ---------------------------------------------------------------------------
__global__ void __launch_bounds__(512, 1) f2_kernel()
{
    extern __shared__ float sm[];
    float* Cs = sm;                  // 32 x 1024
    float* Ps = sm + 32768;          // 16 x 1024 AV partials
    int t = threadIdx.x, lane = t & 31, w = t >> 5;   // w: 0..15
    int rt = blockIdx.x, bh = blockIdx.y;
    int row0 = rt * 32;
    int n = lane >> 2, pi = lane & 3;
    int kq = pi * 2;

    #pragma unroll 1
    for (int m = 0; m < 2; m++) {
        // B-frags for this pass only: [rh 4][hi/lo 2][ks 2][reg 2] = 32 regs
        unsigned B[4][2][2][2];
        int slice = m ? 7 : 0;
        #pragma unroll
        for (int rh = 0; rh < 4; rh++) {
            const uint2* qp = g_projp[slice][bh][row0 + rh * 8 + n];
            uint2 u0 = qp[pi],     u1 = qp[pi + 4];
            uint2 u2 = qp[pi + 8], u3 = qp[pi + 12];
            B[rh][0][0][0] = u0.x; B[rh][1][0][0] = u0.y;
            B[rh][0][0][1] = u1.x; B[rh][1][0][1] = u1.y;
            B[rh][0][1][0] = u2.x; B[rh][1][1][0] = u2.y;
            B[rh][0][1][1] = u3.x; B[rh][1][1][1] = u3.y;
        }
        const uint2* Kp = &g_projp[m ? 8 : 1][bh][0][0];

        #pragma unroll 1
        for (int j = 0; j < 4; j++) {
            int col0 = (j * 16 + w) * 16;
            const uint2* r0p = Kp + (size_t)(col0 + n) * 16;
            const uint2* r1p = Kp + (size_t)(col0 + n + 8) * 16;
            float acc[16];
            #pragma unroll
            for (int e = 0; e < 16; e++) acc[e] = 0.f;
            #pragma unroll
            for (int ks = 0; ks < 2; ks++) {
                int ip = ks * 8 + pi;
                uint2 a0 = r0p[ip],     a1 = r1p[ip];
                uint2 a2 = r0p[ip + 4], a3 = r1p[ip + 4];
                #pragma unroll
                for (int rh = 0; rh < 4; rh++) {
                    mma_bf16(acc[rh*4+0], acc[rh*4+1], acc[rh*4+2], acc[rh*4+3],
                             a0.x, a1.x, a2.x, a3.x,
                             B[rh][0][ks][0], B[rh][0][ks][1]);   // hi*hi
                    mma_bf16(acc[rh*4+0], acc[rh*4+1], acc[rh*4+2], acc[rh*4+3],
                             a0.y, a1.y, a2.y, a3.y,
                             B[rh][0][ks][0], B[rh][0][ks][1]);   // lo*hi
                    mma_bf16(acc[rh*4+0], acc[rh*4+1], acc[rh*4+2], acc[rh*4+3],
                             a0.x, a1.x, a2.x, a3.x,
                             B[rh][1][ks][0], B[rh][1][ks][1]);   // hi*lo
                }
            }
            int c = col0 + n;
            if (m == 0) {
                #pragma unroll
                for (int rh = 0; rh < 4; rh++) {
                    int q = rh * 8 + kq;
                    Cs[q * 1024 + c]           = 0.1f * acc[rh*4+0];
                    Cs[(q + 1) * 1024 + c]     = 0.1f * acc[rh*4+1];
                    Cs[q * 1024 + c + 8]       = 0.1f * acc[rh*4+2];
                    Cs[(q + 1) * 1024 + c + 8] = 0.1f * acc[rh*4+3];
                }
            } else {
                #pragma unroll
                for (int rh = 0; rh < 4; rh++) {
                    int q = rh * 8 + kq;
                    const float* mrow = &g_mask[bh][(size_t)(row0 + q) * 1024];
                    Cs[q * 1024 + c]           += acc[rh*4+0] * mrow[c];
                    Cs[(q + 1) * 1024 + c]     += acc[rh*4+1] * mrow[1024 + c];
                    Cs[q * 1024 + c + 8]       += acc[rh*4+2] * mrow[c + 8];
                    Cs[(q + 1) * 1024 + c + 8] += acc[rh*4+3] * mrow[1024 + c + 8];
                }
            }
        }
        // no sync needed between passes: same thread owns the same Cs cells
    }
    __syncthreads();

    // softmax: warp w owns rows w and w+16
    warp_softmax_row2(Cs + w * 1024, Cs + (w + 16) * 1024, lane);
    __syncthreads();

    // ---- AV: warp w owns j-slice [64w, 64w+64), partials over 32 rows -----
    // Warp-coalesced V reads (for fixed j the warp reads 128 contiguous B).
    const float* Vsrc = &g_v[bh][0][0];
    int d = lane;
    float acc[32];
    #pragma unroll
    for (int i = 0; i < 32; i++) acc[i] = 0.f;
    int base = w * 64;
    #pragma unroll 1
    for (int jj = 0; jj < 64; jj += 4) {
        int j = base + jj;
        float v0 = Vsrc[(size_t)(j + 0) * 32 + d];
        float v1 = Vsrc[(size_t)(j + 1) * 32 + d];
        float v2 = Vsrc[(size_t)(j + 2) * 32 + d];
        float v3 = Vsrc[(size_t)(j + 3) * 32 + d];
        #pragma unroll
        for (int i = 0; i < 32; i++) {
            float4 c4 = *(const float4*)(Cs + i * 1024 + j);
            acc[i] += c4.x * v0 + c4.y * v1 + c4.z * v2 + c4.w * v3;
        }
    }
    #pragma unroll
    for (int i = 0; i < 32; i++) Ps[w * 1024 + i * 32 + d] = acc[i];
    __syncthreads();
    // reduce over 16 warps: thread -> rows (w, w+16), dim lane
    float s0 = 0.f, s1 = 0.f;
    #pragma unroll
    for (int p = 0; p < 16; p++) {
        s0 += Ps[p * 1024 + w * 32 + lane];
        s1 += Ps[p * 1024 + (w + 16) * 32 + lane];
    }
    int b = bh >> 3, hh = bh & 7;
    g_attn_pre[((row0 + w) * 4 + b) * 256 + hh * 32 + lane] = s0;
    g_attn_pre[((row0 + w + 16) * 4 + b) * 256 + hh * 32 + lane] = s1;
}

// ---------------------------------------------------------------------------
// Kernel 4: out-projection via staged HMMA (double-buffered, R15-proven)
// ---------------------------------------------------------------------------
__global__ void __launch_bounds__(256) outproj_hmma_kernel(
        const float* __restrict__ W, const float* __restrict__ bias,
        float* __restrict__ out)
{
    extern __shared__ char smc[];
    int ct = blockIdx.x, rt = blockIdx.y;
    int t = threadIdx.x, lane = t & 31, w = t >> 5;
    int wm = w & 3, wn = w >> 2;

    float acc[2][4][4];
    staged_hmma_128x64(g_attn_pre + (size_t)(rt * 128) * 256,
                       W + (size_t)(ct * 64) * 256, smc, t, lane, w, acc);

    #pragma unroll
    for (int rt2 = 0; rt2 < 2; rt2++) {
        int rbase = rt * 128 + wm * 32 + rt2 * 16 + (lane >> 2);
        #pragma unroll
        for (int g = 0; g < 4; g++) {
            int cbase = ct * 64 + wn * 32 + g * 8 + (lane & 3) * 2;
            float b0 = bias[cbase], b1 = bias[cbase + 1];
            #pragma unroll
            for (int half = 0; half < 2; half++) {
                int r = rbase + half * 8;
                *(float2*)(out + (size_t)r * 256 + cbase) =
                    make_float2(acc[rt2][g][half * 2 + 0] + b0,
                                acc[rt2][g][half * 2 + 1] + b1);
            }
        }
    }
}

// ---------------------------------------------------------------------------
// Kernel 5: consistent_mask = sum over bh of g_mask (float4 vectorized)
// ---------------------------------------------------------------------------
__global__ void __launch_bounds__(256) mask_reduce_kernel(float* __restrict__ out)
{
    int i4 = (blockIdx.x * 256 + threadIdx.x) * 4;
    float4 s = {0.f, 0.f, 0.f, 0.f};
    #pragma unroll
    for (int bh = 0; bh < 32; bh++) {
        float4 v = *(const float4*)&g_mask[bh][i4];
        s.x += v.x; s.y += v.y; s.z += v.z; s.w += v.w;
    }
    *(float4*)(out + i4) = s;
}

// ---------------------------------------------------------------------------
extern "C" void kernel_launch(void* const* d_in, const int* in_sizes, int n_in,
                              void* d_out, int out_size)
{
    const float* q   = (const float*)d_in[0];
    const float* k   = (const float*)d_in[1];
    const float* v   = (const float*)d_in[2];
    const float* ipw = (const float*)d_in[3];
    const float* ipb = (const float*)d_in[4];
    const float* ow  = (const float*)d_in[5];
    const float* ob  = (const float*)d_in[6];
    float* out = (float*)d_out;

    cudaFuncSetAttribute(proj_hmma_kernel, cudaFuncAttributeMaxDynamicSharedMemorySize, 61440);
    cudaFuncSetAttribute(outproj_hmma_kernel, cudaFuncAttributeMaxDynamicSharedMemorySize, 61440);
    cudaFuncSetAttribute(f1_kernel, cudaFuncAttributeMaxDynamicSharedMemorySize, 131072);
    cudaFuncSetAttribute(f2_kernel, cudaFuncAttributeMaxDynamicSharedMemorySize, 196608);

    proj_hmma_kernel<<<dim3(36, 32), 256, 61440>>>(q, k, v, ipw, ipb);
    f1_kernel<<<dim3(64, 32), 512, 131072>>>();
    f2_kernel<<<dim3(32, 32), 512, 196608>>>();
    outproj_hmma_kernel<<<dim3(4, 32), 256, 61440>>>(ow, ob, out);
    mask_reduce_kernel<<<1024, 256>>>(out + 1048576);
}

// round 17
// speedup vs baseline: 1.0229x; 1.0229x over previous
#include <cuda_runtime.h>
#include <cuda_bf16.h>

#define SCALING 0.17677669529663687f

// ---------------------------------------------------------------------------
// Scratch (static device globals — allowed; no runtime allocation)
// g_projp[j][bh][s][k]: .x = bf16x2 hi(dims 2k,2k+1), .y = bf16x2 lo
// ---------------------------------------------------------------------------
__device__ uint2 g_projp[9][32][1024][16];          // interleaved hi/lo planes
__device__ float g_v[32][1024][32];                 // V fp32 (AV)
__device__ float g_mask[32][1024 * 1024];           // local_mask
__device__ float g_attn_pre[4096 * 256];            // pre-out-proj fp32

// ---------------------------------------------------------------------------
// mma.sync m16n8k16 bf16 (HMMA), D/C fp32
// ---------------------------------------------------------------------------
__device__ __forceinline__ void mma_bf16(
    float& d0, float& d1, float& d2, float& d3,
    unsigned a0, unsigned a1, unsigned a2, unsigned a3,
    unsigned b0, unsigned b1)
{
    asm volatile(
        "mma.sync.aligned.m16n8k16.row.col.f32.bf16.bf16.f32 "
        "{%0,%1,%2,%3}, {%4,%5,%6,%7}, {%8,%9}, {%0,%1,%2,%3};\n"
        : "+f"(d0), "+f"(d1), "+f"(d2), "+f"(d3)
        : "r"(a0), "r"(a1), "r"(a2), "r"(a3), "r"(b0), "r"(b1));
}
__device__ __forceinline__ unsigned s2u(const void* p) {
    unsigned a;
    asm("{ .reg .u64 t; cvta.to.shared.u64 t, %1; cvt.u32.u64 %0, t; }"
        : "=r"(a) : "l"(p));
    return a;
}
__device__ __forceinline__ void ldsm_x4(unsigned r[4], unsigned addr) {
    asm volatile("ldmatrix.sync.aligned.m8n8.x4.shared.b16 {%0,%1,%2,%3}, [%4];"
        : "=r"(r[0]), "=r"(r[1]), "=r"(r[2]), "=r"(r[3]) : "r"(addr));
}

// fast packed conversion: one cvt.rn.bf16x2.f32 converts TWO fp32.
// bf2pack(a, b): low half = bf16(a), high half = bf16(b)  (RN, same as before)
__device__ __forceinline__ unsigned bf2pack(float a, float b) {
    unsigned r;
    asm("cvt.rn.bf16x2.f32 %0, %1, %2;" : "=r"(r) : "f"(b), "f"(a));
    return r;
}
__device__ __forceinline__ float bf16lo_f(unsigned p) {
    return __uint_as_float(p << 16);
}
__device__ __forceinline__ float bf16hi_f(unsigned p) {
    return __uint_as_float(p & 0xFFFF0000u);
}

// ---------------------------------------------------------------------------
// warp helpers (R6-proven)
// ---------------------------------------------------------------------------
__device__ __forceinline__ void warp_iscan2(float& a, float& b, int lane) {
    #pragma unroll
    for (int o = 1; o < 32; o <<= 1) {
        float ua = __shfl_up_sync(0xffffffffu, a, o);
        float ub = __shfl_up_sync(0xffffffffu, b, o);
        if (lane >= o) { a += ua; b += ub; }
    }
}
__device__ __forceinline__ void warp_softmax_row2(float* r0, float* r1, int lane) {
    float m0 = -1e30f, m1 = -1e30f;
    #pragma unroll
    for (int q = 0; q < 32; q++) {
        m0 = fmaxf(m0, r0[q * 32 + lane]);
        m1 = fmaxf(m1, r1[q * 32 + lane]);
    }
    #pragma unroll
    for (int o = 16; o; o >>= 1) {
        m0 = fmaxf(m0, __shfl_xor_sync(0xffffffffu, m0, o));
        m1 = fmaxf(m1, __shfl_xor_sync(0xffffffffu, m1, o));
    }
    float s0 = 0.f, s1 = 0.f;
    #pragma unroll
    for (int q = 0; q < 32; q++) {
        float e0 = __expf(r0[q * 32 + lane] - m0);
        float e1 = __expf(r1[q * 32 + lane] - m1);
        r0[q * 32 + lane] = e0;
        r1[q * 32 + lane] = e1;
        s0 += e0; s1 += e1;
    }
    #pragma unroll
    for (int o = 16; o; o >>= 1) {
        s0 += __shfl_xor_sync(0xffffffffu, s0, o);
        s1 += __shfl_xor_sync(0xffffffffu, s1, o);
    }
    float i0 = 1.0f / s0, i1 = 1.0f / s1;
    #pragma unroll
    for (int q = 0; q < 32; q++) {
        r0[q * 32 + lane] *= i0;
        r1[q * 32 + lane] *= i1;
    }
}

// ---------------------------------------------------------------------------
// convert helper: float4 -> 4 hi bf16 + 4 lo bf16 (packed cvt path, ~6 ops)
// ---------------------------------------------------------------------------
__device__ __forceinline__ void split_store4(char* dh, char* dl, float4 v) {
    unsigned h01 = bf2pack(v.x, v.y);
    unsigned h23 = bf2pack(v.z, v.w);
    *(unsigned*)(dh)     = h01;
    *(unsigned*)(dh + 4) = h23;
    *(unsigned*)(dl)     = bf2pack(v.x - bf16lo_f(h01), v.y - bf16hi_f(h01));
    *(unsigned*)(dl + 4) = bf2pack(v.z - bf16lo_f(h23), v.w - bf16hi_f(h23));
}

// ===========================================================================
// Shared staged-HMMA GEMM body, DOUBLE-BUFFERED (R15-proven):
// C[128 x 64] tile of  Xf32 @ Wf32^T.  Two 30720 B buffers.
// ===========================================================================
#define BUF_SZ 30720

__device__ __forceinline__ void stage_buf(char* buf,
        const float* __restrict__ Xbase, const float* __restrict__ Wbase,
        int ch, int t)
{
    char* SAh = buf;
    char* SAl = buf + 10240;
    char* SBh = buf + 20480;
    char* SBl = buf + 25600;
    int r = t >> 3, c = (t & 7) * 4;
    #pragma unroll
    for (int p = 0; p < 4; p++) {
        int rr = r + p * 32;
        float4 v = *(const float4*)(Xbase + (size_t)rr * 256 + ch * 32 + c);
        split_store4(SAh + rr * 80 + c * 2, SAl + rr * 80 + c * 2, v);
    }
    #pragma unroll
    for (int p = 0; p < 2; p++) {
        int rr = r + p * 32;
        float4 v = *(const float4*)(Wbase + (size_t)rr * 256 + ch * 32 + c);
        split_store4(SBh + rr * 80 + c * 2, SBl + rr * 80 + c * 2, v);
    }
}

__device__ __forceinline__ void staged_hmma_128x64(
        const float* __restrict__ Xbase, const float* __restrict__ Wbase,
        char* smc, int t, int lane, int w, float acc[2][4][4])
{
    int wm = w & 3, wn = w >> 2;

    #pragma unroll
    for (int a = 0; a < 2; a++)
        #pragma unroll
        for (int b = 0; b < 4; b++)
            #pragma unroll
            for (int c = 0; c < 4; c++) acc[a][b][c] = 0.f;

    stage_buf(smc, Xbase, Wbase, 0, t);
    __syncthreads();

    #pragma unroll 1
    for (int ch = 0; ch < 8; ch++) {
        char* cur = smc + (ch & 1) * BUF_SZ;
        char* nxt = smc + ((ch + 1) & 1) * BUF_SZ;
        if (ch < 7) stage_buf(nxt, Xbase, Wbase, ch + 1, t);

        char* SBh = cur + 20480;
        char* SBl = cur + 25600;
        unsigned sAh = s2u(cur), sAl = s2u(cur + 10240);

        unsigned ah[2][2][4], al[2][2][4];
        #pragma unroll
        for (int rt2 = 0; rt2 < 2; rt2++) {
            unsigned off = (unsigned)((wm * 32 + rt2 * 16 + (lane & 15)) * 80
                                      + (lane >> 4) * 16);
            ldsm_x4(ah[rt2][0], sAh + off);
            ldsm_x4(ah[rt2][1], sAh + off + 32);
            ldsm_x4(al[rt2][0], sAl + off);
            ldsm_x4(al[rt2][1], sAl + off + 32);
        }
        #pragma unroll
        for (int g = 0; g < 4; g++) {
            int nr = wn * 32 + g * 8 + (lane >> 2);
            int cb = (lane & 3) * 4;
            #pragma unroll
            for (int ks = 0; ks < 2; ks++) {
                unsigned bh0 = *(const unsigned*)(SBh + nr * 80 + cb + ks * 32);
                unsigned bh1 = *(const unsigned*)(SBh + nr * 80 + cb + ks * 32 + 16);
                unsigned bl0 = *(const unsigned*)(SBl + nr * 80 + cb + ks * 32);
                unsigned bl1 = *(const unsigned*)(SBl + nr * 80 + cb + ks * 32 + 16);
                #pragma unroll
                for (int rt2 = 0; rt2 < 2; rt2++) {
                    mma_bf16(acc[rt2][g][0], acc[rt2][g][1], acc[rt2][g][2], acc[rt2][g][3],
                             ah[rt2][ks][0], ah[rt2][ks][1], ah[rt2][ks][2], ah[rt2][ks][3],
                             bh0, bh1);
                    mma_bf16(acc[rt2][g][0], acc[rt2][g][1], acc[rt2][g][2], acc[rt2][g][3],
                             al[rt2][ks][0], al[rt2][ks][1], al[rt2][ks][2], al[rt2][ks][3],
                             bh0, bh1);
                    mma_bf16(acc[rt2][g][0], acc[rt2][g][1], acc[rt2][g][2], acc[rt2][g][3],
                             ah[rt2][ks][0], ah[rt2][ks][1], ah[rt2][ks][2], ah[rt2][ks][3],
                             bl0, bl1);
                }
            }
        }
        __syncthreads();
    }
}

// ---------------------------------------------------------------------------
// Kernel 1: packed in-projection (staged HMMA) -> interleaved planes + g_v
// ---------------------------------------------------------------------------
__global__ void __launch_bounds__(256) proj_hmma_kernel(
        const float* __restrict__ xq, const float* __restrict__ xk,
        const float* __restrict__ xv, const float* __restrict__ W,
        const float* __restrict__ bias)
{
    extern __shared__ char smc[];
    int ct = blockIdx.x, rt = blockIdx.y;
    int j = ct >> 2;
    const float* X = (j == 2) ? xv
                   : ((j == 1 || j == 4 || j == 6 || j == 8) ? xk : xq);
    int t = threadIdx.x, lane = t & 31, w = t >> 5;
    int wm = w & 3, wn = w >> 2;

    float acc[2][4][4];
    staged_hmma_128x64(X + (size_t)(rt * 128) * 256,
                       W + (size_t)(ct * 64) * 256, smc, t, lane, w, acc);

    float scale = (j == 0 || j == 7) ? SCALING : 1.0f;
    #pragma unroll
    for (int rt2 = 0; rt2 < 2; rt2++) {
        int rbase = rt * 128 + wm * 32 + rt2 * 16 + (lane >> 2);
        #pragma unroll
        for (int g = 0; g < 4; g++) {
            int cbase = ct * 64 + wn * 32 + g * 8 + (lane & 3) * 2;
            int eo = cbase - j * 256;
            #pragma unroll
            for (int half = 0; half < 2; half++) {
                int r = rbase + half * 8;
                float v0 = (acc[rt2][g][half * 2 + 0] + bias[cbase]) * scale;
                float v1 = (acc[rt2][g][half * 2 + 1] + bias[cbase + 1]) * scale;
                int s = r >> 2, b = r & 3;
                int bhp = b * 8 + (eo >> 5), dd = eo & 31;
                uint2 val;
                val.x = bf2pack(v0, v1);
                val.y = bf2pack(v0 - bf16lo_f(val.x), v1 - bf16hi_f(val.x));
                g_projp[j][bhp][s][dd >> 1] = val;
                if (j == 2) *(float2*)&g_v[bhp][s][dd] = make_float2(v0, v1);
            }
        }
    }
}

// ---------------------------------------------------------------------------
// Kernel F1: per (bh, 16 rows), 512 threads / 16 warps (R12-proven)
// ---------------------------------------------------------------------------
__global__ void __launch_bounds__(512, 1) f1_kernel()
{
    extern __shared__ float sm[];
    float* Ls = sm;                  // 16 x 1024
    float* Rs = sm + 16384;          // 16 x 1024
    int t = threadIdx.x, lane = t & 31, w = t >> 5;   // w: 0..15
    int rt = blockIdx.x, bh = blockIdx.y;
    int row0 = rt * 16;
    int n = lane >> 2, pi = lane & 3;

    unsigned B[2][2][2][2][2];
    #pragma unroll
    for (int m = 0; m < 2; m++) {
        int slice = m ? 5 : 3;
        #pragma unroll
        for (int rh = 0; rh < 2; rh++) {
            const uint2* qp = g_projp[slice][bh][row0 + rh * 8 + n];
            uint2 u0 = qp[pi],     u1 = qp[pi + 4];
            uint2 u2 = qp[pi + 8], u3 = qp[pi + 12];
            B[m][rh][0][0][0] = u0.x; B[m][rh][1][0][0] = u0.y;
            B[m][rh][0][0][1] = u1.x; B[m][rh][1][0][1] = u1.y;
            B[m][rh][0][1][0] = u2.x; B[m][rh][1][1][0] = u2.y;
            B[m][rh][0][1][1] = u3.x; B[m][rh][1][1][1] = u3.y;
        }
    }

    #pragma unroll 1
    for (int m = 0; m < 2; m++) {
        const uint2* Kp = &g_projp[m ? 6 : 4][bh][0][0];
        float* Obuf = m ? Rs : Ls;
        #pragma unroll 1
        for (int j = 0; j < 4; j++) {
            int col0 = (j * 16 + w) * 16;
            const uint2* r0p = Kp + (size_t)(col0 + n) * 16;
            const uint2* r1p = Kp + (size_t)(col0 + n + 8) * 16;
            float d[2][4] = {};
            #pragma unroll
            for (int ks = 0; ks < 2; ks++) {
                int ip = ks * 8 + pi;
                uint2 a0 = r0p[ip],     a1 = r1p[ip];
                uint2 a2 = r0p[ip + 4], a3 = r1p[ip + 4];
                #pragma unroll
                for (int rh = 0; rh < 2; rh++) {
                    mma_bf16(d[rh][0], d[rh][1], d[rh][2], d[rh][3],
                             a0.x, a1.x, a2.x, a3.x,
                             B[m][rh][0][ks][0], B[m][rh][0][ks][1]);
                    mma_bf16(d[rh][0], d[rh][1], d[rh][2], d[rh][3],
                             a0.y, a1.y, a2.y, a3.y,
                             B[m][rh][0][ks][0], B[m][rh][0][ks][1]);
                    mma_bf16(d[rh][0], d[rh][1], d[rh][2], d[rh][3],
                             a0.x, a1.x, a2.x, a3.x,
                             B[m][rh][1][ks][0], B[m][rh][1][ks][1]);
                }
            }
            int c = col0 + n;
            #pragma unroll
            for (int rh = 0; rh < 2; rh++) {
                int q = rh * 8 + pi * 2;
                Obuf[q * 1024 + c]           = d[rh][0];
                Obuf[(q + 1) * 1024 + c]     = d[rh][1];
                Obuf[q * 1024 + c + 8]       = d[rh][2];
                Obuf[(q + 1) * 1024 + c + 8] = d[rh][3];
            }
        }
    }
    __syncthreads();

    float* Lrow = Ls + w * 1024;
    float* Rrow = Rs + w * 1024;
    warp_softmax_row2(Lrow, Rrow, lane);

    float sL[32], sR[32];
    float runPL = 0.f, runPR = 0.f;
    #pragma unroll
    for (int q = 0; q < 32; q++) {
        float vL = Lrow[q * 32 + lane];
        float vR = Rrow[q * 32 + lane];
        float pL = vL, pR = vR;
        warp_iscan2(pL, pR, lane);
        float BL = __shfl_sync(0xffffffffu, pL, 31);
        float BR = __shfl_sync(0xffffffffu, pR, 31);
        runPL += pL;
        runPR += pR;
        Lrow[q * 32 + lane] = runPL;
        Rrow[q * 32 + lane] = runPR;
        sL[q] = BL - pL + vL;
        sR[q] = BR - pR + vR;
    }
    float* mout = &g_mask[bh][(size_t)(row0 + w) * 1024];
    float runSL = 0.f, runSR = 0.f;
    #pragma unroll
    for (int q = 31; q >= 0; q--) {
        runSL += sL[q];
        runSR += sR[q];
        mout[q * 32 + lane] = Lrow[q * 32 + lane] * runSR
                            + runSL * Rrow[q * 32 + lane];
    }
}

// ---------------------------------------------------------------------------
// Kernel F2: per (bh, 16 rows): global+local logits (uint2 direct-LDG HMMA)
// + mask combine -> softmax -> AV (SIMT fp32).  dyn smem 81920 B, 2 CTAs/SM
// (R12-proven + mask-row prefetch before the K8 MMA block)
// ---------------------------------------------------------------------------
__global__ void __launch_bounds__(256, 2) f2_kernel()
{
    extern __shared__ float sm[];
    float* Cs = sm;
    float* Ps = sm + 16384;
    int t = threadIdx.x, lane = t & 31, w = t >> 5;
    int rt = blockIdx.x, bh = blockIdx.y;
    int row0 = rt * 16;
    int n = lane >> 2, pi = lane & 3;

    unsigned B[2][2][2][2][2];
    #pragma unroll
    for (int mtx = 0; mtx < 2; mtx++) {
        int slice = mtx ? 7 : 0;
        #pragma unroll
        for (int rh = 0; rh < 2; rh++) {
            const uint2* qp = g_projp[slice][bh][row0 + rh * 8 + n];
            uint2 u0 = qp[pi],     u1 = qp[pi + 4];
            uint2 u2 = qp[pi + 8], u3 = qp[pi + 12];
            B[mtx][rh][0][0][0] = u0.x; B[mtx][rh][1][0][0] = u0.y;
            B[mtx][rh][0][0][1] = u1.x; B[mtx][rh][1][0][1] = u1.y;
            B[mtx][rh][0][1][0] = u2.x; B[mtx][rh][1][1][0] = u2.y;
            B[mtx][rh][0][1][1] = u3.x; B[mtx][rh][1][1][1] = u3.y;
        }
    }

    const uint2* K1 = &g_projp[1][bh][0][0];
    const uint2* K8 = &g_projp[8][bh][0][0];

    #pragma unroll 1
    for (int j = 0; j < 8; j++) {
        int col0 = (j * 8 + w) * 16;
        int c = col0 + n;
        int kq = pi * 2;
        float g[8] = {}, lc[8] = {};
        {
            const uint2* r0p = K1 + (size_t)(col0 + n) * 16;
            const uint2* r1p = K1 + (size_t)(col0 + n + 8) * 16;
            #pragma unroll
            for (int ks = 0; ks < 2; ks++) {
                int ip = ks * 8 + pi;
                uint2 a0 = r0p[ip],     a1 = r1p[ip];
                uint2 a2 = r0p[ip + 4], a3 = r1p[ip + 4];
                #pragma unroll
                for (int rh = 0; rh < 2; rh++) {
                    mma_bf16(g[rh*4+0], g[rh*4+1], g[rh*4+2], g[rh*4+3],
                             a0.x, a1.x, a2.x, a3.x,
                             B[0][rh][0][ks][0], B[0][rh][0][ks][1]);
                    mma_bf16(g[rh*4+0], g[rh*4+1], g[rh*4+2], g[rh*4+3],
                             a0.y, a1.y, a2.y, a3.y,
                             B[0][rh][0][ks][0], B[0][rh][0][ks][1]);
                    mma_bf16(g[rh*4+0], g[rh*4+1], g[rh*4+2], g[rh*4+3],
                             a0.x, a1.x, a2.x, a3.x,
                             B[0][rh][1][ks][0], B[0][rh][1][ks][1]);
                }
            }
        }
        // prefetch mask rows (latency hides behind the K8 MMA block below)
        float mpre[2][4];
        #pragma unroll
        for (int rh = 0; rh < 2; rh++) {
            int q = rh * 8 + kq;
            const float* mrow = &g_mask[bh][(size_t)(row0 + q) * 1024];
            mpre[rh][0] = mrow[c];
            mpre[rh][1] = mrow[1024 + c];
            mpre[rh][2] = mrow[c + 8];
            mpre[rh][3] = mrow[1024 + c + 8];
        }
        {
            const uint2* r0p = K8 + (size_t)(col0 + n) * 16;
            const uint2* r1p = K8 + (size_t)(col0 + n + 8) * 16;
            #pragma unroll
            for (int ks = 0; ks < 2; ks++) {
                int ip = ks * 8 + pi;
                uint2 a0 = r0p[ip],     a1 = r1p[ip];
                uint2 a2 = r0p[ip + 4], a3 = r1p[ip + 4];
                #pragma unroll
                for (int rh = 0; rh < 2; rh++) {
                    mma_bf16(lc[rh*4+0], lc[rh*4+1], lc[rh*4+2], lc[rh*4+3],
                             a0.x, a1.x, a2.x, a3.x,
                             B[1][rh][0][ks][0], B[1][rh][0][ks][1]);
                    mma_bf16(lc[rh*4+0], lc[rh*4+1], lc[rh*4+2], lc[rh*4+3],
                             a0.y, a1.y, a2.y, a3.y,
                             B[1][rh][0][ks][0], B[1][rh][0][ks][1]);
                    mma_bf16(lc[rh*4+0], lc[rh*4+1], lc[rh*4+2], lc[rh*4+3],
                             a0.x, a1.x, a2.x, a3.x,
                             B[1][rh][1][ks][0], B[1][rh][1][ks][1]);
                }
            }
        }
        #pragma unroll
        for (int rh = 0; rh < 2; rh++) {
            int q = rh * 8 + kq;
            Cs[q * 1024 + c]           = 0.1f * g[rh*4+0] + lc[rh*4+0] * mpre[rh][0];
            Cs[(q + 1) * 1024 + c]     = 0.1f * g[rh*4+1] + lc[rh*4+1] * mpre[rh][1];
            Cs[q * 1024 + c + 8]       = 0.1f * g[rh*4+2] + lc[rh*4+2] * mpre[rh][2];
            Cs[(q + 1) * 1024 + c + 8] = 0.1f * g[rh*4+3] + lc[rh*4+3] * mpre[rh][3];
        }
    }
    __syncthreads();

    warp_softmax_row2(Cs + w * 1024, Cs + (w + 8) * 1024, lane);
    __syncthreads();

    // ---- AV: thread (d=lane, jp=w) owns j-slice [128w, 128w+128) ----------
    const float* Vsrc = &g_v[bh][0][0];
    int d = lane, jp = w;
    float acc[16];
    #pragma unroll
    for (int i = 0; i < 16; i++) acc[i] = 0.f;
    int base = jp * 128;
    #pragma unroll 2
    for (int jj = 0; jj < 128; jj += 4) {
        int j = base + jj;
        float v0 = Vsrc[(size_t)(j + 0) * 32 + d];
        float v1 = Vsrc[(size_t)(j + 1) * 32 + d];
        float v2 = Vsrc[(size_t)(j + 2) * 32 + d];
        float v3 = Vsrc[(size_t)(j + 3) * 32 + d];
        #pragma unroll
        for (int i = 0; i < 16; i++) {
            float4 c4 = *(const float4*)(Cs + i * 1024 + j);
            acc[i] += c4.x * v0 + c4.y * v1 + c4.z * v2 + c4.w * v3;
        }
    }
    #pragma unroll
    for (int i = 0; i < 16; i++) Ps[jp * 512 + i * 32 + d] = acc[i];
    __syncthreads();
    float s0 = 0.f, s1 = 0.f;
    #pragma unroll
    for (int p = 0; p < 8; p++) {
        s0 += Ps[p * 512 + w * 32 + lane];
        s1 += Ps[p * 512 + (w + 8) * 32 + lane];
    }
    int b = bh >> 3, hh = bh & 7;
    g_attn_pre[((row0 + w) * 4 + b) * 256 + hh * 32 + lane] = s0;
    g_attn_pre[((row0 + w + 8) * 4 + b) * 256 + hh * 32 + lane] = s1;
}

// ---------------------------------------------------------------------------
// Kernel 4: out-projection via staged HMMA (double-buffered, R15-proven)
// ---------------------------------------------------------------------------
__global__ void __launch_bounds__(256) outproj_hmma_kernel(
        const float* __restrict__ W, const float* __restrict__ bias,
        float* __restrict__ out)
{
    extern __shared__ char smc[];
    int ct = blockIdx.x, rt = blockIdx.y;
    int t = threadIdx.x, lane = t & 31, w = t >> 5;
    int wm = w & 3, wn = w >> 2;

    float acc[2][4][4];
    staged_hmma_128x64(g_attn_pre + (size_t)(rt * 128) * 256,
                       W + (size_t)(ct * 64) * 256, smc, t, lane, w, acc);

    #pragma unroll
    for (int rt2 = 0; rt2 < 2; rt2++) {
        int rbase = rt * 128 + wm * 32 + rt2 * 16 + (lane >> 2);
        #pragma unroll
        for (int g = 0; g < 4; g++) {
            int cbase = ct * 64 + wn * 32 + g * 8 + (lane & 3) * 2;
            float b0 = bias[cbase], b1 = bias[cbase + 1];
            #pragma unroll
            for (int half = 0; half < 2; half++) {
                int r = rbase + half * 8;
                *(float2*)(out + (size_t)r * 256 + cbase) =
                    make_float2(acc[rt2][g][half * 2 + 0] + b0,
                                acc[rt2][g][half * 2 + 1] + b1);
            }
        }
    }
}

// ---------------------------------------------------------------------------
// Kernel 5: consistent_mask = sum over bh of g_mask (float4 vectorized)
// ---------------------------------------------------------------------------
__global__ void __launch_bounds__(256) mask_reduce_kernel(float* __restrict__ out)
{
    int i4 = (blockIdx.x * 256 + threadIdx.x) * 4;
    float4 s = {0.f, 0.f, 0.f, 0.f};
    #pragma unroll
    for (int bh = 0; bh < 32; bh++) {
        float4 v = *(const float4*)&g_mask[bh][i4];
        s.x += v.x; s.y += v.y; s.z += v.z; s.w += v.w;
    }
    *(float4*)(out + i4) = s;
}

// ---------------------------------------------------------------------------
extern "C" void kernel_launch(void* const* d_in, const int* in_sizes, int n_in,
                              void* d_out, int out_size)
{
    const float* q   = (const float*)d_in[0];
    const float* k   = (const float*)d_in[1];
    const float* v   = (const float*)d_in[2];
    const float* ipw = (const float*)d_in[3];
    const float* ipb = (const float*)d_in[4];
    const float* ow  = (const float*)d_in[5];
    const float* ob  = (const float*)d_in[6];
    float* out = (float*)d_out;

    cudaFuncSetAttribute(proj_hmma_kernel, cudaFuncAttributeMaxDynamicSharedMemorySize, 61440);
    cudaFuncSetAttribute(outproj_hmma_kernel, cudaFuncAttributeMaxDynamicSharedMemorySize, 61440);
    cudaFuncSetAttribute(f1_kernel, cudaFuncAttributeMaxDynamicSharedMemorySize, 131072);
    cudaFuncSetAttribute(f2_kernel, cudaFuncAttributeMaxDynamicSharedMemorySize, 81920);

    proj_hmma_kernel<<<dim3(36, 32), 256, 61440>>>(q, k, v, ipw, ipb);
    f1_kernel<<<dim3(64, 32), 512, 131072>>>();
    f2_kernel<<<dim3(64, 32), 256, 81920>>>();
    outproj_hmma_kernel<<<dim3(4, 32), 256, 61440>>>(ow, ob, out);
    mask_reduce_kernel<<<1024, 256>>>(out + 1048576);
}